// round 1
// baseline (speedup 1.0000x reference)
#include <cuda_runtime.h>
#include <math.h>

#define B_   16
#define SQ_  128
#define SV_  128
#define DQ_  512
#define DV_  512
#define U_   256
#define CTX_ELEMS (B_*SQ_*DV_)   // 1048576 floats, context first, weights after

// Scratch (allocation-free rule: __device__ globals)
__device__ float g_s1[B_*SQ_*U_];   // [b][q][u]
__device__ float g_s2[B_*SV_*U_];   // [b][v][u]

__device__ __forceinline__ float tanh_fast(float x) {
    float y;
    asm("tanh.approx.f32 %0, %1;" : "=f"(y) : "f"(x));
    return y;
}

// -------------------------------------------------------------------------
// GEMM: C[M,256] = A[M,512] * W[512,256] + bias  (row-major everywhere)
// 64x64x16 block tile, 256 threads, 4x4 microtile, reg-prefetch double buffer.
// which==0 -> writes g_s1, which==1 -> writes g_s2
// -------------------------------------------------------------------------
__global__ __launch_bounds__(256) void gemm_bias_kernel(
    const float* __restrict__ A, const float* __restrict__ W,
    const float* __restrict__ bias, int which)
{
    __shared__ float As[16][68];   // padded: conflict-light stores, aligned f4 reads
    __shared__ float Ws[16][64];

    float* __restrict__ C = which ? g_s2 : g_s1;

    const int tid  = threadIdx.x;
    const int bm   = blockIdx.y * 64;
    const int bn   = blockIdx.x * 64;
    const int tx   = tid & 15;          // n-dir
    const int ty   = tid >> 4;          // m-dir
    const int arow = tid >> 2;          // 0..63
    const int ak   = (tid & 3) << 2;    // 0,4,8,12
    const int wrow = tid >> 4;          // 0..15
    const int wn   = (tid & 15) << 2;   // 0..60

    const float* Ap = A + (size_t)(bm + arow) * DQ_ + ak;
    const float* Wp = W + (size_t)wrow * U_ + bn + wn;

    float4 ap = *(const float4*)Ap;
    float4 wp = *(const float4*)Wp;

    float c[4][4];
    #pragma unroll
    for (int i = 0; i < 4; i++)
        #pragma unroll
        for (int j = 0; j < 4; j++) c[i][j] = 0.f;

    #pragma unroll 1
    for (int kt = 0; kt < DQ_/16; ++kt) {
        As[ak+0][arow] = ap.x;
        As[ak+1][arow] = ap.y;
        As[ak+2][arow] = ap.z;
        As[ak+3][arow] = ap.w;
        *(float4*)&Ws[wrow][wn] = wp;
        __syncthreads();
        if (kt + 1 < DQ_/16) {
            ap = *(const float4*)(Ap + (kt+1)*16);
            wp = *(const float4*)(Wp + (size_t)(kt+1)*16*U_);
        }
        #pragma unroll
        for (int k = 0; k < 16; k++) {
            float4 a4 = *(const float4*)&As[k][ty << 2];
            float4 w4 = *(const float4*)&Ws[k][tx << 2];
            float av[4] = {a4.x, a4.y, a4.z, a4.w};
            float wv[4] = {w4.x, w4.y, w4.z, w4.w};
            #pragma unroll
            for (int i = 0; i < 4; i++)
                #pragma unroll
                for (int j = 0; j < 4; j++)
                    c[i][j] += av[i] * wv[j];
        }
        __syncthreads();
    }

    float4 bv = *(const float4*)(bias + bn + (tx << 2));
    float bb[4] = {bv.x, bv.y, bv.z, bv.w};
    #pragma unroll
    for (int i = 0; i < 4; i++) {
        float4 o;
        o.x = c[i][0] + bb[0];
        o.y = c[i][1] + bb[1];
        o.z = c[i][2] + bb[2];
        o.w = c[i][3] + bb[3];
        *(float4*)&C[(size_t)(bm + (ty << 2) + i) * U_ + bn + (tx << 2)] = o;
    }
}

// -------------------------------------------------------------------------
// Fused attention: per CTA = (batch b, 16-query tile).
//   smem: s2[b] (v-major, stride 260 for conflict-free f4 reads), s1 tile,
//         Vw, scores. 256 threads: (v = tid&127, q-half = tid>>7).
//   score -> softmax over v -> weights out -> context GEMV (v split in half).
// -------------------------------------------------------------------------
#define S2STRIDE 260

__global__ __launch_bounds__(256, 1) void attn_kernel(
    const float* __restrict__ values, const float* __restrict__ Vw,
    float* __restrict__ out)
{
    extern __shared__ float sm[];
    float* s2s = sm;                         // 128*260 = 33280 floats
    float* s1s = sm + 128 * S2STRIDE;        // 16*256  = 4096
    float* vws = s1s + 16 * U_;              // 256
    float* sc  = vws + U_;                   // 16*128  = 2048

    const int tid = threadIdx.x;
    const int b   = blockIdx.x >> 3;
    const int q0  = (blockIdx.x & 7) << 4;

    // --- stage s2[b], s1 tile, Vw into smem ---
    const float4* s2g4 = (const float4*)(g_s2 + (size_t)b * SV_ * U_);
    for (int i = tid; i < SV_ * (U_/4); i += 256) {
        int v = i >> 6, uq = i & 63;
        *(float4*)&s2s[v * S2STRIDE + (uq << 2)] = s2g4[i];
    }
    const float4* s1g4 = (const float4*)(g_s1 + ((size_t)b * SQ_ + q0) * U_);
    for (int i = tid; i < 16 * (U_/4); i += 256)
        ((float4*)s1s)[i] = s1g4[i];
    if (tid < U_/4)
        ((float4*)vws)[tid] = ((const float4*)Vw)[tid];
    __syncthreads();

    // --- scores: score[q][v] = sum_u Vw[u]*tanh(s1[q][u] + s2[v][u]) ---
    {
        const int v  = tid & 127;
        const int qh = tid >> 7;              // 0 or 1 -> q in [qh*8, qh*8+8)
        float acc[8] = {0,0,0,0,0,0,0,0};
        const float* s1q = s1s + (qh << 3) * U_;
        const float* s2r = s2s + v * S2STRIDE;
        #pragma unroll 2
        for (int u = 0; u < U_; u += 4) {
            float4 f2 = *(const float4*)(s2r + u);
            float4 wv = *(const float4*)(vws + u);
            #pragma unroll
            for (int qi = 0; qi < 8; qi++) {
                float4 s1v = *(const float4*)(s1q + qi * U_ + u);
                acc[qi] += wv.x * tanh_fast(s1v.x + f2.x)
                         + wv.y * tanh_fast(s1v.y + f2.y)
                         + wv.z * tanh_fast(s1v.z + f2.z)
                         + wv.w * tanh_fast(s1v.w + f2.w);
            }
        }
        #pragma unroll
        for (int qi = 0; qi < 8; qi++)
            sc[((qh << 3) + qi) * SV_ + v] = acc[qi];
    }
    __syncthreads();

    // --- softmax over v (axis Sv); each warp handles 2 q rows ---
    {
        const int w = tid >> 5, lane = tid & 31;
        #pragma unroll
        for (int qq = 0; qq < 2; qq++) {
            int q = (w << 1) + qq;
            float x0 = sc[q*SV_ +      lane];
            float x1 = sc[q*SV_ + 32 + lane];
            float x2 = sc[q*SV_ + 64 + lane];
            float x3 = sc[q*SV_ + 96 + lane];
            float m = fmaxf(fmaxf(x0, x1), fmaxf(x2, x3));
            #pragma unroll
            for (int off = 16; off; off >>= 1)
                m = fmaxf(m, __shfl_xor_sync(0xffffffffu, m, off));
            float e0 = __expf(x0 - m), e1 = __expf(x1 - m);
            float e2 = __expf(x2 - m), e3 = __expf(x3 - m);
            float s = (e0 + e1) + (e2 + e3);
            #pragma unroll
            for (int off = 16; off; off >>= 1)
                s += __shfl_xor_sync(0xffffffffu, s, off);
            float inv = 1.0f / s;
            e0 *= inv; e1 *= inv; e2 *= inv; e3 *= inv;
            sc[q*SV_ +      lane] = e0;
            sc[q*SV_ + 32 + lane] = e1;
            sc[q*SV_ + 64 + lane] = e2;
            sc[q*SV_ + 96 + lane] = e3;
            float* wout = out + CTX_ELEMS + (size_t)(b * SQ_ + q0 + q) * SV_;
            wout[lane]      = e0;
            wout[32 + lane] = e1;
            wout[64 + lane] = e2;
            wout[96 + lane] = e3;
        }
    }
    __syncthreads();

    // --- context[q][d] = sum_v w[q][v] * values[b][v][d]; v split in halves ---
    {
        const int half = tid >> 7;            // v-range half
        const int dg   = tid & 127;           // float4 group over DV
        float4 acc[16];
        #pragma unroll
        for (int q = 0; q < 16; q++) acc[q] = make_float4(0.f, 0.f, 0.f, 0.f);

        const float* vb  = values + ((size_t)(b * SV_) + (half << 6)) * DV_ + (dg << 2);
        const float* scv = sc + (half << 6);
        #pragma unroll 4
        for (int vv = 0; vv < 64; vv++) {
            float4 val = *(const float4*)(vb + (size_t)vv * DV_);
            #pragma unroll
            for (int q = 0; q < 16; q++) {
                float wq = scv[q * SV_ + vv];
                acc[q].x += wq * val.x;
                acc[q].y += wq * val.y;
                acc[q].z += wq * val.z;
                acc[q].w += wq * val.w;
            }
        }
        float4* cbuf = (float4*)s2s;   // reuse s2 smem region (done with it)
        if (half) {
            #pragma unroll
            for (int q = 0; q < 16; q++) cbuf[q * 128 + dg] = acc[q];
        }
        __syncthreads();
        if (!half) {
            #pragma unroll
            for (int q = 0; q < 16; q++) {
                float4 o = cbuf[q * 128 + dg];
                o.x += acc[q].x; o.y += acc[q].y;
                o.z += acc[q].z; o.w += acc[q].w;
                *(float4*)&out[(size_t)(b * SQ_ + q0 + q) * DV_ + (dg << 2)] = o;
            }
        }
    }
}

// -------------------------------------------------------------------------
extern "C" void kernel_launch(void* const* d_in, const int* in_sizes, int n_in,
                              void* d_out, int out_size)
{
    const float* query  = (const float*)d_in[0];
    const float* values = (const float*)d_in[1];
    const float* W1     = (const float*)d_in[2];
    const float* b1     = (const float*)d_in[3];
    const float* W2     = (const float*)d_in[4];
    const float* b2     = (const float*)d_in[5];
    const float* Vw     = (const float*)d_in[6];
    // d_in[7] = Vb: softmax is shift-invariant and score itself is not an
    // output, so Vb provably cancels. Unused.
    float* out = (float*)d_out;

    dim3 gemm_grid(U_/64, (B_*SQ_)/64);            // 4 x 32 = 128 CTAs
    gemm_bias_kernel<<<gemm_grid, 256>>>(query,  W1, b1, 0);
    gemm_bias_kernel<<<gemm_grid, 256>>>(values, W2, b2, 1);

    const size_t smbytes =
        (size_t)(128 * S2STRIDE + 16 * U_ + U_ + 16 * SV_) * sizeof(float); // 158720
    cudaFuncSetAttribute(attn_kernel,
                         cudaFuncAttributeMaxDynamicSharedMemorySize,
                         (int)smbytes);
    attn_kernel<<<B_ * 8, 256, smbytes>>>(values, Vw, out);
}